// round 15
// baseline (speedup 1.0000x reference)
#include <cuda_runtime.h>
#include <cuda_fp16.h>
#include <cstdint>

#define NB    4096
#define KCH   3
#define FIN   16
#define FOUT  16
#define TT    12
#define BATCH 2
#define COLS  384                       /* BATCH*FOUT*TT */
#define OUT_ELEMS (BATCH*NB*FOUT*TT)    /* 1572864 */

#define BM 128
#define BN 128
#define BKK 32
#define NSTEPS (NB/BKK)                 /* 128 */
#define A_PAD 132
#define B_PADH 40
#define AS_BYTES (BKK*A_PAD*4)          /* 16896 */
#define BS_BYTES (BN*B_PADH*2)          /* 10240 */
#define STAGE_BYTES (AS_BYTES + BS_BYTES) /* 27136 */
#define STAGES 4
#define SMEM_BYTES (STAGES*STAGE_BYTES)   /* 108544 */

/* zT kernel: 64 m-rows per block, one (m-pair, t) per thread, k split */
#define ZM   64
#define XROW 193                         /* padded floats per m-row (192 data) */
#define Z_SMEM_BYTES ((ZM*XROW + FIN*FOUT)*4)   /* 50432 */

__device__ __half g_zTh[(size_t)KCH*COLS*NB];   // [k][col][m], m contiguous, fp16
__device__ float  g_part[(size_t)KCH*NB*COLS];  // [k][n][col], fp32 partials

// ---------------------------------------------------------------------------
__device__ __forceinline__ uint32_t smem_u32(const void* p) {
    uint32_t a;
    asm("{ .reg .u64 t; cvta.to.shared.u64 t, %1; cvt.u32.u64 %0, t; }" : "=r"(a) : "l"(p));
    return a;
}
#define CPASYNC16(d, s) asm volatile("cp.async.cg.shared.global [%0], [%1], 16;" :: "r"(d), "l"(s) : "memory")
#define CP_COMMIT()     asm volatile("cp.async.commit_group;" ::: "memory")

__device__ __forceinline__ void mma_f16(float* c, const uint32_t* a, const uint32_t* b) {
    asm volatile(
        "mma.sync.aligned.m16n8k16.row.col.f32.f16.f16.f32 "
        "{%0,%1,%2,%3}, {%4,%5,%6,%7}, {%8,%9}, {%0,%1,%2,%3};"
        : "+f"(c[0]), "+f"(c[1]), "+f"(c[2]), "+f"(c[3])
        : "r"(a[0]), "r"(a[1]), "r"(a[2]), "r"(a[3]), "r"(b[0]), "r"(b[1]));
}
__device__ __forceinline__ uint32_t packh(float lo, float hi) {
    uint32_t r;
    asm("cvt.rn.f16x2.f32 %0, %1, %2;" : "=r"(r) : "f"(hi), "f"(lo));
    return r;
}

// ---------------------------------------------------------------------------
// Fused lhs + zT (k split across blockIdx.z):
//   ls[f,o] = 0.5 * sum_j Gamma[j,f,o] * xj[j,k]       (k = blockIdx.z)
//   zTh[k][col=b*192+o*12+t][m] = fp16( sum_f x[b,m,f,t] * ls[f,o] )
// grid (NB/ZM, BATCH, KCH) = (64, 2, 3), 384 threads; thread = (m-pair, t).
// ---------------------------------------------------------------------------
__global__ void __launch_bounds__(384) zT_kernel(const float* __restrict__ x,
                                                 const float* __restrict__ Gamma,
                                                 const float* __restrict__ xj) {
    extern __shared__ float zs[];                 // xs[ZM][XROW] then ls[256]
    float* xs = zs;
    float* ls = zs + ZM*XROW;
    const int tid = threadIdx.x;                  // 0..383
    const int mc = blockIdx.x, b = blockIdx.y, k = blockIdx.z;

    // lhs slice for this k (256 entries)
    if (tid < FIN*FOUT) {
        float s = 0.f;
#pragma unroll
        for (int j = 0; j < KCH; ++j) s += Gamma[j*FIN*FOUT + tid] * xj[j*KCH + k];
        ls[tid] = 0.5f * s;
    }

    // stage x[b, mc*ZM .. +ZM): 12288 floats = 3072 float4, coalesced
    const float4* xsrc = (const float4*)(x + ((size_t)(b*NB + mc*ZM)) * (FIN*TT));
#pragma unroll
    for (int i = tid; i < ZM*(FIN*TT)/4; i += 384) {
        float4 v = xsrc[i];
        int e = i * 4;
        int m = e / (FIN*TT), c = e % (FIN*TT);
        float* d = xs + m*XROW + c;
        d[0] = v.x; d[1] = v.y; d[2] = v.z; d[3] = v.w;
    }
    __syncthreads();

    const int L = tid & 31, t = tid >> 5;         // t in 0..11
    const int m0 = 2*L;                           // even m of the pair
    float xr0[FIN], xr1[FIN];
#pragma unroll
    for (int f = 0; f < FIN; ++f) {
        xr0[f] = xs[ m0      *XROW + f*TT + t];
        xr1[f] = xs[(m0 + 1) *XROW + f*TT + t];
    }
    const size_t mg = (size_t)(mc*ZM + m0);
    const size_t colbase = (size_t)k*COLS + b*(FOUT*TT) + t;
#pragma unroll
    for (int o = 0; o < FOUT; ++o) {
        float s0 = 0.f, s1 = 0.f;
#pragma unroll
        for (int f = 0; f < FIN; ++f) {
            s0 += xr0[f] * ls[f*FOUT + o];
            s1 += xr1[f] * ls[f*FOUT + o];
        }
        *(__half2*)(g_zTh + (colbase + o*TT)*NB + mg) =
            __halves2half2(__float2half_rn(s0), __float2half_rn(s1));
    }
}

// ---------------------------------------------------------------------------
// GEMM: g_part[kb][n][col] = sum_m cheb[kb][m][n] * zTh[kb][col][m]
// fp16 mma.sync m16n8k16, 128x128x32 tile, 64x64 warp tile, 4-stage cp.async.
// PDL: A-prefetch (cheb, independent of zT) issued BEFORE
// cudaGridDependencySynchronize(); B-loads after. Group layout:
//   g0 = {A0,A1,A2,B0}, g1 = {B1}, g2 = {B2}  -> wait_group 2 semantics intact.
// ---------------------------------------------------------------------------
__global__ void __launch_bounds__(128, 2) gemm_kernel(const float* __restrict__ cheb) {
    extern __shared__ char smc[];
    const int tid  = threadIdx.x;
    const int lane = tid & 31, wid = tid >> 5;
    const int warp_m = wid >> 1, warp_n = wid & 1;      // 2x2 warp grid
    const int n0 = blockIdx.x * BM;
    const int c0 = blockIdx.y * BN;
    const int kb = blockIdx.z;

    const float*  Ag = cheb  + (size_t)kb*NB*NB + n0;              // + m*NB
    const __half* Bg = g_zTh + (size_t)kb*COLS*NB + (size_t)c0*NB; // + col*NB + m

    auto load_A = [&](int stage, int m0) {
        char* Sa = smc + stage * STAGE_BYTES;
#pragma unroll
        for (int j = 0; j < 8; ++j) {
            int i = tid + 128*j;
            int m = i >> 5, c = i & 31;
            CPASYNC16(smem_u32(Sa + (m*A_PAD + c*4)*4), Ag + (size_t)(m0 + m)*NB + c*4);
        }
    };
    auto load_B = [&](int stage, int m0) {
        char* Sb = smc + stage * STAGE_BYTES + AS_BYTES;
#pragma unroll
        for (int j = 0; j < 4; ++j) {
            int i = tid + 128*j;
            int col = i >> 2, ch = i & 3;
            CPASYNC16(smem_u32(Sb + col*(B_PADH*2) + ch*16), Bg + (size_t)col*NB + m0 + ch*8);
        }
    };
    auto load_stage = [&](int stage, int m0) { load_A(stage, m0); load_B(stage, m0); };

    // A-prefetch of all 3 preload stages BEFORE the dependency sync (cheb only)
    load_A(0, 0); load_A(1, BKK); load_A(2, 2*BKK);
#if __CUDA_ARCH__ >= 900
    cudaGridDependencySynchronize();
#endif
    load_B(0, 0);       CP_COMMIT();   // g0 = {A0,A1,A2,B0}
    load_B(1, BKK);     CP_COMMIT();   // g1 = {B1}
    load_B(2, 2*BKK);   CP_COMMIT();   // g2 = {B2}

    float acc[4][8][4];
#pragma unroll
    for (int mi = 0; mi < 4; ++mi)
#pragma unroll
        for (int ni = 0; ni < 8; ++ni)
#pragma unroll
            for (int q = 0; q < 4; ++q) acc[mi][ni][q] = 0.f;

    const int nb0 = warp_m * 64;
    const int cb0 = warp_n * 64;
    const int r4  = lane >> 2;   // 0..7
    const int l4  = lane & 3;    // 0..3

    for (int it = 0; it < NSTEPS; ++it) {
        const int buf = it & 3;
        asm volatile("cp.async.wait_group 2;" ::: "memory");
        __syncthreads();
        const float*  As  = (const float*)(smc + buf * STAGE_BYTES);
        const __half* Bsh = (const __half*)(smc + buf * STAGE_BYTES + AS_BYTES);
#pragma unroll
        for (int ks = 0; ks < 2; ++ks) {
            const int kk = ks * 16;
            const float* Ar = As + (kk + 2*l4)*A_PAD + nb0 + r4;
            uint32_t a[4][4];
#pragma unroll
            for (int mi = 0; mi < 4; ++mi) {
                const int cofs = mi*16;
                a[mi][0] = packh(Ar[cofs              ], Ar[cofs + A_PAD      ]);
                a[mi][1] = packh(Ar[cofs + 8          ], Ar[cofs + A_PAD + 8  ]);
                a[mi][2] = packh(Ar[cofs + 8*A_PAD    ], Ar[cofs + 9*A_PAD    ]);
                a[mi][3] = packh(Ar[cofs + 8*A_PAD + 8], Ar[cofs + 9*A_PAD + 8]);
            }
            const __half* Br = Bsh + kk + 2*l4;
            uint32_t b[8][2];
#pragma unroll
            for (int ni = 0; ni < 8; ++ni) {
                const int cc = cb0 + ni*8 + r4;
                b[ni][0] = *(const uint32_t*)(Br + cc*B_PADH);
                b[ni][1] = *(const uint32_t*)(Br + cc*B_PADH + 8);
            }
#pragma unroll
            for (int mi = 0; mi < 4; ++mi)
#pragma unroll
                for (int ni = 0; ni < 8; ++ni)
                    mma_f16(acc[mi][ni], a[mi], b[ni]);
        }
        // stage (it+3)&3 == (it-1)&3 was fully consumed before the barrier above
        if (it + 3 < NSTEPS) load_stage((it + 3) & 3, (it + 3) * BKK);
        CP_COMMIT();
    }

    // ---- epilogue: fp32 per-k partials
    float* P = g_part + (size_t)kb*NB*COLS;
#pragma unroll
    for (int mi = 0; mi < 4; ++mi) {
        const int row0 = n0 + nb0 + mi*16 + r4;
#pragma unroll
        for (int ni = 0; ni < 8; ++ni) {
            const int col = c0 + cb0 + ni*8 + 2*l4;
            *(float2*)&P[(size_t) row0      *COLS + col] = make_float2(acc[mi][ni][0], acc[mi][ni][1]);
            *(float2*)&P[(size_t)(row0 + 8) *COLS + col] = make_float2(acc[mi][ni][2], acc[mi][ni][3]);
        }
    }
}

// ---------------------------------------------------------------------------
// out = relu( sum_kb g_part ), float4, 4 elements per thread, batched loads
// ---------------------------------------------------------------------------
__global__ void relu_sum_kernel(float4* __restrict__ out) {
#if __CUDA_ARCH__ >= 900
    cudaGridDependencySynchronize();
#endif
    const int base = blockIdx.x * blockDim.x * 4 + threadIdx.x;
    const float4* p = (const float4*)g_part;
    float4 v0[4], v1[4], v2[4];
    int idxs[4];
#pragma unroll
    for (int u = 0; u < 4; ++u) {
        int idx = base + u * blockDim.x;
        idxs[u] = idx;
        if (idx < OUT_ELEMS/4) {
            int b  = idx / (NB*48);
            int r  = idx % (NB*48);
            int n  = r / 48;
            int c4 = r % 48;
            size_t off = (size_t)n*96 + b*48 + c4;
            v0[u] = p[off];
            v1[u] = p[(size_t)NB*96 + off];
            v2[u] = p[2*(size_t)NB*96 + off];
        }
    }
#pragma unroll
    for (int u = 0; u < 4; ++u) {
        if (idxs[u] < OUT_ELEMS/4) {
            float4 o;
            o.x = fmaxf(v0[u].x + v1[u].x + v2[u].x, 0.f);
            o.y = fmaxf(v0[u].y + v1[u].y + v2[u].y, 0.f);
            o.z = fmaxf(v0[u].z + v1[u].z + v2[u].z, 0.f);
            o.w = fmaxf(v0[u].w + v1[u].w + v2[u].w, 0.f);
            out[idxs[u]] = o;
        }
    }
}

// ---------------------------------------------------------------------------
extern "C" void kernel_launch(void* const* d_in, const int* in_sizes, int n_in,
                              void* d_out, int out_size) {
    const float* x     = (const float*)d_in[0];
    const float* cheb  = (const float*)d_in[1];
    const float* xj    = (const float*)d_in[2];
    const float* Gamma = (const float*)d_in[3];

    cudaFuncSetAttribute(gemm_kernel, cudaFuncAttributeMaxDynamicSharedMemorySize, SMEM_BYTES);
    cudaFuncSetAttribute(zT_kernel,   cudaFuncAttributeMaxDynamicSharedMemorySize, Z_SMEM_BYTES);

    zT_kernel<<<dim3(NB/ZM, BATCH, KCH), 384, Z_SMEM_BYTES>>>(x, Gamma, xj);

    // gemm with programmatic dependent launch (overlaps zT tail with A-prefetch)
    {
        cudaLaunchAttribute attr[1];
        attr[0].id = cudaLaunchAttributeProgrammaticStreamSerialization;
        attr[0].val.programmaticStreamSerializationAllowed = 1;
        cudaLaunchConfig_t cfg = {};
        cfg.gridDim = dim3(32, 3, 3);
        cfg.blockDim = dim3(128, 1, 1);
        cfg.dynamicSmemBytes = SMEM_BYTES;
        cfg.stream = 0;
        cfg.attrs = attr;
        cfg.numAttrs = 1;
        cudaLaunchKernelEx(&cfg, gemm_kernel, cheb);
    }

    // relu with PDL (hides launch latency under gemm tail)
    {
        cudaLaunchAttribute attr[1];
        attr[0].id = cudaLaunchAttributeProgrammaticStreamSerialization;
        attr[0].val.programmaticStreamSerializationAllowed = 1;
        cudaLaunchConfig_t cfg = {};
        cfg.gridDim = dim3((OUT_ELEMS/4 + 1023)/1024, 1, 1);
        cfg.blockDim = dim3(256, 1, 1);
        cfg.dynamicSmemBytes = 0;
        cfg.stream = 0;
        cfg.attrs = attr;
        cfg.numAttrs = 1;
        cudaLaunchKernelEx(&cfg, relu_sum_kernel, (float4*)d_out);
    }
}

// round 16
// speedup vs baseline: 1.0229x; 1.0229x over previous
#include <cuda_runtime.h>
#include <cuda_fp16.h>
#include <cstdint>

#define NB    4096
#define KCH   3
#define FIN   16
#define FOUT  16
#define TT    12
#define BATCH 2
#define COLS  384                       /* BATCH*FOUT*TT */
#define OUT_ELEMS (BATCH*NB*FOUT*TT)    /* 1572864 */

#define BM 128
#define BN 128
#define BKK 32
#define NSTEPS (NB/BKK)                 /* 128 */
#define A_PAD 132
#define B_PADH 40
#define AS_BYTES (BKK*A_PAD*4)          /* 16896 */
#define BS_BYTES (BN*B_PADH*2)          /* 10240 */
#define STAGE_BYTES (AS_BYTES + BS_BYTES) /* 27136 */
#define STAGES 4
#define SMEM_BYTES (STAGES*STAGE_BYTES)   /* 108544 */

/* zT kernel: 64 m-rows per block, one (m-pair, t) per thread, k split */
#define ZM   64
#define XROW 193                         /* padded floats per m-row (192 data) */
#define Z_SMEM_BYTES ((ZM*XROW + FIN*FOUT)*4)   /* 50432 */

__device__ __half g_zTh[(size_t)KCH*COLS*NB];   // [k][col][m], m contiguous, fp16
__device__ float  g_part[(size_t)KCH*NB*COLS];  // [k][n][col], fp32 partials

// ---------------------------------------------------------------------------
__device__ __forceinline__ uint32_t smem_u32(const void* p) {
    uint32_t a;
    asm("{ .reg .u64 t; cvta.to.shared.u64 t, %1; cvt.u32.u64 %0, t; }" : "=r"(a) : "l"(p));
    return a;
}
#define CPASYNC16(d, s) asm volatile("cp.async.cg.shared.global [%0], [%1], 16;" :: "r"(d), "l"(s) : "memory")
/* evict_first hinted copy for the zero-reuse cheb stream */
#define CPASYNC16_EF(d, s, pol) \
    asm volatile("cp.async.cg.shared.global.L2::cache_hint [%0], [%1], 16, %2;" \
                 :: "r"(d), "l"(s), "l"(pol) : "memory")
#define CP_COMMIT()     asm volatile("cp.async.commit_group;" ::: "memory")

__device__ __forceinline__ void mma_f16(float* c, const uint32_t* a, const uint32_t* b) {
    asm volatile(
        "mma.sync.aligned.m16n8k16.row.col.f32.f16.f16.f32 "
        "{%0,%1,%2,%3}, {%4,%5,%6,%7}, {%8,%9}, {%0,%1,%2,%3};"
        : "+f"(c[0]), "+f"(c[1]), "+f"(c[2]), "+f"(c[3])
        : "r"(a[0]), "r"(a[1]), "r"(a[2]), "r"(a[3]), "r"(b[0]), "r"(b[1]));
}
__device__ __forceinline__ uint32_t packh(float lo, float hi) {
    uint32_t r;
    asm("cvt.rn.f16x2.f32 %0, %1, %2;" : "=r"(r) : "f"(hi), "f"(lo));
    return r;
}

// ---------------------------------------------------------------------------
// Fused lhs + zT (k split across blockIdx.z):
//   ls[f,o] = 0.5 * sum_j Gamma[j,f,o] * xj[j,k]       (k = blockIdx.z)
//   zTh[k][col=b*192+o*12+t][m] = fp16( sum_f x[b,m,f,t] * ls[f,o] )
// grid (NB/ZM, BATCH, KCH) = (64, 2, 3), 384 threads; thread = (m-pair, t).
// ---------------------------------------------------------------------------
__global__ void __launch_bounds__(384) zT_kernel(const float* __restrict__ x,
                                                 const float* __restrict__ Gamma,
                                                 const float* __restrict__ xj) {
    extern __shared__ float zs[];                 // xs[ZM][XROW] then ls[256]
    float* xs = zs;
    float* ls = zs + ZM*XROW;
    const int tid = threadIdx.x;                  // 0..383
    const int mc = blockIdx.x, b = blockIdx.y, k = blockIdx.z;

    // lhs slice for this k (256 entries)
    if (tid < FIN*FOUT) {
        float s = 0.f;
#pragma unroll
        for (int j = 0; j < KCH; ++j) s += Gamma[j*FIN*FOUT + tid] * xj[j*KCH + k];
        ls[tid] = 0.5f * s;
    }

    // stage x[b, mc*ZM .. +ZM): 12288 floats = 3072 float4, coalesced
    const float4* xsrc = (const float4*)(x + ((size_t)(b*NB + mc*ZM)) * (FIN*TT));
#pragma unroll
    for (int i = tid; i < ZM*(FIN*TT)/4; i += 384) {
        float4 v = xsrc[i];
        int e = i * 4;
        int m = e / (FIN*TT), c = e % (FIN*TT);
        float* d = xs + m*XROW + c;
        d[0] = v.x; d[1] = v.y; d[2] = v.z; d[3] = v.w;
    }
    __syncthreads();

    const int L = tid & 31, t = tid >> 5;         // t in 0..11
    const int m0 = 2*L;                           // even m of the pair
    float xr0[FIN], xr1[FIN];
#pragma unroll
    for (int f = 0; f < FIN; ++f) {
        xr0[f] = xs[ m0      *XROW + f*TT + t];
        xr1[f] = xs[(m0 + 1) *XROW + f*TT + t];
    }
    const size_t mg = (size_t)(mc*ZM + m0);
    const size_t colbase = (size_t)k*COLS + b*(FOUT*TT) + t;
#pragma unroll
    for (int o = 0; o < FOUT; ++o) {
        float s0 = 0.f, s1 = 0.f;
#pragma unroll
        for (int f = 0; f < FIN; ++f) {
            s0 += xr0[f] * ls[f*FOUT + o];
            s1 += xr1[f] * ls[f*FOUT + o];
        }
        *(__half2*)(g_zTh + (colbase + o*TT)*NB + mg) =
            __halves2half2(__float2half_rn(s0), __float2half_rn(s1));
    }
}

// ---------------------------------------------------------------------------
// GEMM: g_part[kb][n][col] = sum_m cheb[kb][m][n] * zTh[kb][col][m]
// fp16 mma.sync m16n8k16, 128x128x32 tile, 64x64 warp tile, 4-stage cp.async,
// single __syncthreads per iteration. cheb (A) loads carry an
// L2::evict_first hint so the 201MB zero-reuse stream doesn't evict the
// L2-resident zTh (32x reuse) and g_part (read back by relu_sum).
// ---------------------------------------------------------------------------
__global__ void __launch_bounds__(128, 2) gemm_kernel(const float* __restrict__ cheb) {
    extern __shared__ char smc[];
    const int tid  = threadIdx.x;
    const int lane = tid & 31, wid = tid >> 5;
    const int warp_m = wid >> 1, warp_n = wid & 1;      // 2x2 warp grid
    const int n0 = blockIdx.x * BM;
    const int c0 = blockIdx.y * BN;
    const int kb = blockIdx.z;

    uint64_t pol;
    asm("createpolicy.fractional.L2::evict_first.b64 %0, 1.0;" : "=l"(pol));

    const float*  Ag = cheb  + (size_t)kb*NB*NB + n0;              // + m*NB
    const __half* Bg = g_zTh + (size_t)kb*COLS*NB + (size_t)c0*NB; // + col*NB + m

    auto load_stage = [&](int stage, int m0) {
        char* Sa = smc + stage * STAGE_BYTES;
        char* Sb = Sa + AS_BYTES;
#pragma unroll
        for (int j = 0; j < 8; ++j) {
            int i = tid + 128*j;
            int m = i >> 5, c = i & 31;
            CPASYNC16_EF(smem_u32(Sa + (m*A_PAD + c*4)*4),
                         Ag + (size_t)(m0 + m)*NB + c*4, pol);
        }
#pragma unroll
        for (int j = 0; j < 4; ++j) {
            int i = tid + 128*j;
            int col = i >> 2, ch = i & 3;
            CPASYNC16(smem_u32(Sb + col*(B_PADH*2) + ch*16), Bg + (size_t)col*NB + m0 + ch*8);
        }
    };

    load_stage(0, 0);       CP_COMMIT();
    load_stage(1, BKK);     CP_COMMIT();
    load_stage(2, 2*BKK);   CP_COMMIT();

    float acc[4][8][4];
#pragma unroll
    for (int mi = 0; mi < 4; ++mi)
#pragma unroll
        for (int ni = 0; ni < 8; ++ni)
#pragma unroll
            for (int q = 0; q < 4; ++q) acc[mi][ni][q] = 0.f;

    const int nb0 = warp_m * 64;
    const int cb0 = warp_n * 64;
    const int r4  = lane >> 2;   // 0..7
    const int l4  = lane & 3;    // 0..3

    for (int it = 0; it < NSTEPS; ++it) {
        const int buf = it & 3;
        asm volatile("cp.async.wait_group 2;" ::: "memory");
        __syncthreads();
        const float*  As  = (const float*)(smc + buf * STAGE_BYTES);
        const __half* Bsh = (const __half*)(smc + buf * STAGE_BYTES + AS_BYTES);
#pragma unroll
        for (int ks = 0; ks < 2; ++ks) {
            const int kk = ks * 16;
            const float* Ar = As + (kk + 2*l4)*A_PAD + nb0 + r4;
            uint32_t a[4][4];
#pragma unroll
            for (int mi = 0; mi < 4; ++mi) {
                const int cofs = mi*16;
                a[mi][0] = packh(Ar[cofs              ], Ar[cofs + A_PAD      ]);
                a[mi][1] = packh(Ar[cofs + 8          ], Ar[cofs + A_PAD + 8  ]);
                a[mi][2] = packh(Ar[cofs + 8*A_PAD    ], Ar[cofs + 9*A_PAD    ]);
                a[mi][3] = packh(Ar[cofs + 8*A_PAD + 8], Ar[cofs + 9*A_PAD + 8]);
            }
            const __half* Br = Bsh + kk + 2*l4;
            uint32_t b[8][2];
#pragma unroll
            for (int ni = 0; ni < 8; ++ni) {
                const int cc = cb0 + ni*8 + r4;
                b[ni][0] = *(const uint32_t*)(Br + cc*B_PADH);
                b[ni][1] = *(const uint32_t*)(Br + cc*B_PADH + 8);
            }
#pragma unroll
            for (int mi = 0; mi < 4; ++mi)
#pragma unroll
                for (int ni = 0; ni < 8; ++ni)
                    mma_f16(acc[mi][ni], a[mi], b[ni]);
        }
        // stage (it+3)&3 == (it-1)&3 was fully consumed before the barrier above
        if (it + 3 < NSTEPS) load_stage((it + 3) & 3, (it + 3) * BKK);
        CP_COMMIT();
    }

    // ---- epilogue: fp32 per-k partials
    float* P = g_part + (size_t)kb*NB*COLS;
#pragma unroll
    for (int mi = 0; mi < 4; ++mi) {
        const int row0 = n0 + nb0 + mi*16 + r4;
#pragma unroll
        for (int ni = 0; ni < 8; ++ni) {
            const int col = c0 + cb0 + ni*8 + 2*l4;
            *(float2*)&P[(size_t) row0      *COLS + col] = make_float2(acc[mi][ni][0], acc[mi][ni][1]);
            *(float2*)&P[(size_t)(row0 + 8) *COLS + col] = make_float2(acc[mi][ni][2], acc[mi][ni][3]);
        }
    }
}

// ---------------------------------------------------------------------------
// out = relu( sum_kb g_part ), float4, 4 elements per thread, batched loads
// ---------------------------------------------------------------------------
__global__ void relu_sum_kernel(float4* __restrict__ out) {
    const int base = blockIdx.x * blockDim.x * 4 + threadIdx.x;
    const float4* p = (const float4*)g_part;
    float4 v0[4], v1[4], v2[4];
    int idxs[4];
#pragma unroll
    for (int u = 0; u < 4; ++u) {
        int idx = base + u * blockDim.x;
        idxs[u] = idx;
        if (idx < OUT_ELEMS/4) {
            int b  = idx / (NB*48);
            int r  = idx % (NB*48);
            int n  = r / 48;
            int c4 = r % 48;
            size_t off = (size_t)n*96 + b*48 + c4;
            v0[u] = p[off];
            v1[u] = p[(size_t)NB*96 + off];
            v2[u] = p[2*(size_t)NB*96 + off];
        }
    }
#pragma unroll
    for (int u = 0; u < 4; ++u) {
        if (idxs[u] < OUT_ELEMS/4) {
            float4 o;
            o.x = fmaxf(v0[u].x + v1[u].x + v2[u].x, 0.f);
            o.y = fmaxf(v0[u].y + v1[u].y + v2[u].y, 0.f);
            o.z = fmaxf(v0[u].z + v1[u].z + v2[u].z, 0.f);
            o.w = fmaxf(v0[u].w + v1[u].w + v2[u].w, 0.f);
            out[idxs[u]] = o;
        }
    }
}

// ---------------------------------------------------------------------------
extern "C" void kernel_launch(void* const* d_in, const int* in_sizes, int n_in,
                              void* d_out, int out_size) {
    const float* x     = (const float*)d_in[0];
    const float* cheb  = (const float*)d_in[1];
    const float* xj    = (const float*)d_in[2];
    const float* Gamma = (const float*)d_in[3];

    cudaFuncSetAttribute(gemm_kernel, cudaFuncAttributeMaxDynamicSharedMemorySize, SMEM_BYTES);
    cudaFuncSetAttribute(zT_kernel,   cudaFuncAttributeMaxDynamicSharedMemorySize, Z_SMEM_BYTES);

    zT_kernel<<<dim3(NB/ZM, BATCH, KCH), 384, Z_SMEM_BYTES>>>(x, Gamma, xj);
    gemm_kernel<<<dim3(32, 3, 3), 128, SMEM_BYTES>>>(cheb);
    relu_sum_kernel<<<(OUT_ELEMS/4 + 1023)/1024, 256>>>((float4*)d_out);
}